// round 3
// baseline (speedup 1.0000x reference)
#include <cuda_runtime.h>
#include <math.h>

#define TT 512
#define BBATCH 4
#define CC 256
#define NN 2048
#define DD 65536
#define NE 64
#define ROUT 256
#define DECAYv 0.999f
#define GAMv ((float)((1.0 - 0.999) / 2048.0))
#define COMMITv 0.25f

// ---------------- device scratch (no allocations allowed) ----------------
__device__ float g_M[CC*CC];        // W^T W
__device__ float g_G[NE*CC];        // Cents @ W
__device__ float g_A[NE*CC];        // resp^T X
__device__ float g_H[NE*NE];        // Cnew Cnew^T
__device__ float g_cnorm[NE], g_bc[NE], g_s[NE];
__device__ float g_Wtb[CC];
__device__ float g_bb;
__device__ float g_acc[3];          // sum qnorm, sum cross, sum quad
__device__ float g_pw1T[CC*CC];
__device__ float g_XM[NN*CC];
__device__ float g_Y[NN*CC];
__device__ float g_xG[NN*NE];
__device__ float g_qnorm[NN], g_xWtb[NN];
__device__ float g_resp[NN*NE];
__device__ float g_Cnew[NE*DD];     // 16.7 MB

// ---------------- zero accumulators ----------------
__global__ void k_zero() {
    int i = blockIdx.x * blockDim.x + threadIdx.x;
    if (i < CC*CC) g_M[i] = 0.f;
    if (i < NE*CC) { g_G[i] = 0.f; g_A[i] = 0.f; }
    if (i < NE*NE) g_H[i] = 0.f;
    if (i < CC)    g_Wtb[i] = 0.f;
    if (i < NE)    { g_cnorm[i] = 0.f; g_bc[i] = 0.f; g_s[i] = 0.f; }
    if (i == 0)    { g_bb = 0.f; g_acc[0] = 0.f; g_acc[1] = 0.f; g_acc[2] = 0.f; }
}

// ---------------- M = W^T W   (split-K, 64x64 tiles, atomics) ----------------
__global__ void k_gram(const float* __restrict__ W) {
    __shared__ float sa[16][64];
    __shared__ float sb[16][64];
    int tid = threadIdx.x;
    int i0 = blockIdx.x * 64, j0 = blockIdx.y * 64;
    int d0 = blockIdx.z * 2048;
    int ty = tid >> 4, tx = tid & 15;
    float acc[4][4];
#pragma unroll
    for (int r = 0; r < 4; r++)
#pragma unroll
        for (int c = 0; c < 4; c++) acc[r][c] = 0.f;

    for (int ks = 0; ks < 2048; ks += 16) {
#pragma unroll
        for (int l = 0; l < 4; l++) {
            int idx = tid + l * 256;
            int dd = idx >> 6, cc2 = idx & 63;
            const float* row = W + (size_t)(d0 + ks + dd) * CC;
            sa[dd][cc2] = row[i0 + cc2];
            sb[dd][cc2] = row[j0 + cc2];
        }
        __syncthreads();
#pragma unroll
        for (int dd = 0; dd < 16; dd++) {
            float a[4], bv[4];
#pragma unroll
            for (int r = 0; r < 4; r++) a[r] = sa[dd][ty*4 + r];
#pragma unroll
            for (int c = 0; c < 4; c++) bv[c] = sb[dd][tx*4 + c];
#pragma unroll
            for (int r = 0; r < 4; r++)
#pragma unroll
                for (int c = 0; c < 4; c++) acc[r][c] += a[r] * bv[c];
        }
        __syncthreads();
    }
#pragma unroll
    for (int r = 0; r < 4; r++)
#pragma unroll
        for (int c = 0; c < 4; c++)
            atomicAdd(&g_M[(i0 + ty*4 + r) * CC + (j0 + tx*4 + c)], acc[r][c]);
}

// ---------------- G = Cents @ W, plus cnorm, bc, Wtb, bb ----------------
__global__ void k_centW(const float* __restrict__ W, const float* __restrict__ cents,
                        const float* __restrict__ bvec) {
    __shared__ float cs[NE][65];
    __shared__ float bs[64];
    int tid = threadIdx.x;
    int d0 = blockIdx.x * 512;
    float accG[NE];
#pragma unroll
    for (int e = 0; e < NE; e++) accG[e] = 0.f;
    float accWtb = 0.f, accCN = 0.f, accBC = 0.f, accBB = 0.f;

    for (int ds = 0; ds < 512; ds += 64) {
        int dbase = d0 + ds;
#pragma unroll
        for (int l = 0; l < 16; l++) {
            int idx = tid + l * 256;
            int e = idx >> 6, dd = idx & 63;
            cs[e][dd] = cents[(size_t)e * DD + dbase + dd];
        }
        if (tid < 64) bs[tid] = bvec[dbase + tid];
        __syncthreads();

        for (int dd = 0; dd < 64; dd++) {
            float w = W[(size_t)(dbase + dd) * CC + tid];
            accWtb += bs[dd] * w;
#pragma unroll
            for (int e = 0; e < NE; e++) accG[e] += cs[e][dd] * w;
        }
        if (tid < NE) {
            float cn = 0.f, bc = 0.f;
            for (int dd = 0; dd < 64; dd++) { float c = cs[tid][dd]; cn += c*c; bc += c*bs[dd]; }
            accCN += cn; accBC += bc;
        }
        if (tid == 64) {
            float s = 0.f;
            for (int dd = 0; dd < 64; dd++) s += bs[dd]*bs[dd];
            accBB += s;
        }
        __syncthreads();
    }
#pragma unroll
    for (int e = 0; e < NE; e++) atomicAdd(&g_G[e * CC + tid], accG[e]);
    atomicAdd(&g_Wtb[tid], accWtb);
    if (tid < NE) { atomicAdd(&g_cnorm[tid], accCN); atomicAdd(&g_bc[tid], accBC); }
    if (tid == 64) atomicAdd(&g_bb, accBB);
}

// ---------------- transpose pw1 ----------------
__global__ void k_pw1T(const float* __restrict__ pw1) {
    int c = blockIdx.x, k = threadIdx.x;
    g_pw1T[c * CC + k] = pw1[k * CC + c];
}

// ---------------- XM = X@M, Y = X@pw1^T, xG = X@G^T, qnorm, xWtb ----------------
__global__ void k_xsmall(const float* __restrict__ x) {
    __shared__ float xs[8][CC];
    __shared__ float red[256];
    int tid = threadIdx.x;
    int n0 = blockIdx.x * 8;
#pragma unroll
    for (int l = 0; l < 8; l++) {
        int idx = tid + l * 256;
        xs[idx >> 8][idx & 255] = x[(size_t)n0 * CC + idx];
    }
    __syncthreads();

    float acc[8], accY[8];
#pragma unroll
    for (int t = 0; t < 8; t++) { acc[t] = 0.f; accY[t] = 0.f; }
    for (int c = 0; c < CC; c++) {
        float m = g_M[c * CC + tid];
        float p = g_pw1T[c * CC + tid];
#pragma unroll
        for (int t = 0; t < 8; t++) { acc[t] += xs[t][c] * m; accY[t] += xs[t][c] * p; }
    }
#pragma unroll
    for (int t = 0; t < 8; t++) {
        g_XM[(size_t)(n0 + t) * CC + tid] = acc[t];
        g_Y[(size_t)(n0 + t) * CC + tid]  = accY[t];
    }

    float wtb = g_Wtb[tid];
    float bb = g_bb;
    for (int t = 0; t < 8; t++) {
        // qdot = sum_j XM*x
        red[tid] = acc[t] * xs[t][tid];
        __syncthreads();
        for (int s = 128; s >= 1; s >>= 1) { if (tid < s) red[tid] += red[tid + s]; __syncthreads(); }
        float qdot = red[0]; __syncthreads();
        // xwtb = sum_j x*Wtb
        red[tid] = xs[t][tid] * wtb;
        __syncthreads();
        for (int s = 128; s >= 1; s >>= 1) { if (tid < s) red[tid] += red[tid + s]; __syncthreads(); }
        float xwtb = red[0]; __syncthreads();
        if (tid == 0) {
            g_qnorm[n0 + t] = qdot + 2.f * xwtb + bb;
            g_xWtb[n0 + t]  = xwtb;
        }
    }

    // xG: thread = (e, part p of 4)
    int e = tid & 63, p = tid >> 6;
    for (int t = 0; t < 8; t++) {
        float sum = 0.f;
        int cbase = p * 64;
        for (int c = 0; c < 64; c++) sum += xs[t][cbase + c] * g_G[e * CC + cbase + c];
        red[tid] = sum;
        __syncthreads();
        if (p == 0) g_xG[(size_t)(n0 + t) * NE + e] = red[e] + red[64 + e] + red[128 + e] + red[192 + e];
        __syncthreads();
    }
}

// ---------------- resp = softmax((-d2 + gumbel)/tau) ----------------
__global__ void k_resp(const float* __restrict__ u) {
    __shared__ float red[64];
    int n = blockIdx.x, e = threadIdx.x;
    float d2 = g_qnorm[n] + g_cnorm[e] - 2.f * (g_xG[(size_t)n * NE + e] + g_bc[e]);
    float g = -logf(-logf(u[(size_t)n * NE + e]));
    float logit = -d2 + g;   // TAU = 1
    red[e] = logit; __syncthreads();
    for (int s = 32; s >= 1; s >>= 1) { if (e < s) red[e] = fmaxf(red[e], red[e + s]); __syncthreads(); }
    float mx = red[0]; __syncthreads();
    float ex = expf(logit - mx);
    red[e] = ex; __syncthreads();
    for (int s = 32; s >= 1; s >>= 1) { if (e < s) red[e] += red[e + s]; __syncthreads(); }
    g_resp[(size_t)n * NE + e] = ex / red[0];
}

// ---------------- A = resp^T X, s = colsum(resp) ----------------
__global__ void k_A(const float* __restrict__ x) {
    __shared__ float rs[32][NE + 1];
    int tid = threadIdx.x;
    int n0 = blockIdx.x * 32;
#pragma unroll
    for (int l = 0; l < 8; l++) {
        int idx = tid + l * 256;
        rs[idx >> 6][idx & 63] = g_resp[(size_t)(n0 + (idx >> 6)) * NE + (idx & 63)];
    }
    __syncthreads();
    float acc[NE];
#pragma unroll
    for (int e = 0; e < NE; e++) acc[e] = 0.f;
    for (int t = 0; t < 32; t++) {
        float xv = x[(size_t)(n0 + t) * CC + tid];
#pragma unroll
        for (int e = 0; e < NE; e++) acc[e] += rs[t][e] * xv;
    }
#pragma unroll
    for (int e = 0; e < NE; e++) atomicAdd(&g_A[e * CC + tid], acc[e]);
    if (tid < NE) {
        float s = 0.f;
        for (int t = 0; t < 32; t++) s += rs[t][tid];
        atomicAdd(&g_s[tid], s);
    }
}

// ---------------- Cnew = decay*Cents + gam*(A@W^T + s b^T) ----------------
__global__ void k_cnew(const float* __restrict__ W, const float* __restrict__ cents,
                       const float* __restrict__ bvec) {
    __shared__ float Ws[64][65];
    __shared__ float As[64][65];
    int tid = threadIdx.x;
    int d0 = blockIdx.x * 64;
    int te = tid >> 4, td = tid & 15;
    float acc[4][4];
#pragma unroll
    for (int r = 0; r < 4; r++)
#pragma unroll
        for (int q = 0; q < 4; q++) acc[r][q] = 0.f;

    for (int kc = 0; kc < CC; kc += 64) {
#pragma unroll
        for (int l = 0; l < 16; l++) {
            int idx = tid + l * 256;
            int r2 = idx >> 6, c2 = idx & 63;
            Ws[r2][c2] = W[(size_t)(d0 + r2) * CC + kc + c2];
            As[r2][c2] = g_A[r2 * CC + kc + c2];
        }
        __syncthreads();
        for (int kk = 0; kk < 64; kk++) {
            float a[4], wv[4];
#pragma unroll
            for (int r = 0; r < 4; r++) a[r] = As[te*4 + r][kk];
#pragma unroll
            for (int q = 0; q < 4; q++) wv[q] = Ws[td*4 + q][kk];
#pragma unroll
            for (int r = 0; r < 4; r++)
#pragma unroll
                for (int q = 0; q < 4; q++) acc[r][q] += a[r] * wv[q];
        }
        __syncthreads();
    }
#pragma unroll
    for (int r = 0; r < 4; r++) {
        int e = te*4 + r;
        float se = g_s[e];
#pragma unroll
        for (int q = 0; q < 4; q++) {
            int d = d0 + td*4 + q;
            g_Cnew[(size_t)e * DD + d] =
                DECAYv * cents[(size_t)e * DD + d] + GAMv * (acc[r][q] + se * bvec[d]);
        }
    }
}

// ---------------- H = Cnew Cnew^T ----------------
__global__ void k_H() {
    __shared__ float cn[NE][129];
    int tid = threadIdx.x;
    int e1 = tid & 63, g2 = tid >> 6;
    float acc[16];
#pragma unroll
    for (int i = 0; i < 16; i++) acc[i] = 0.f;
    int d0 = blockIdx.x * 512;
    for (int ds = 0; ds < 512; ds += 128) {
#pragma unroll
        for (int l = 0; l < 32; l++) {
            int idx = tid + l * 256;
            cn[idx >> 7][idx & 127] = g_Cnew[(size_t)(idx >> 7) * DD + d0 + ds + (idx & 127)];
        }
        __syncthreads();
        for (int dd = 0; dd < 128; dd++) {
            float v = cn[e1][dd];
#pragma unroll
            for (int i = 0; i < 16; i++) acc[i] += v * cn[g2*16 + i][dd];
        }
        __syncthreads();
    }
#pragma unroll
    for (int i = 0; i < 16; i++) atomicAdd(&g_H[e1 * NE + g2*16 + i], acc[i]);
}

// ---------------- loss partial sums ----------------
__global__ void k_loss() {
    __shared__ float red[64];
    __shared__ float xmw[CC];
    int n = blockIdx.x, e = threadIdx.x;
#pragma unroll
    for (int l = 0; l < 4; l++)
        xmw[e + l*64] = g_XM[(size_t)n * CC + e + l*64] + g_Wtb[e + l*64];
    __syncthreads();
    float P = 0.f;
    for (int c = 0; c < CC; c++) P += xmw[c] * g_A[e * CC + c];
    float r = g_resp[(size_t)n * NE + e];
    float dotne = g_xG[(size_t)n * NE + e] + g_bc[e];
    float cross = r * (DECAYv * dotne + GAMv * (P + g_s[e] * (g_xWtb[n] + g_bb)));
    float he = 0.f;
    for (int e2 = 0; e2 < NE; e2++) he += g_resp[(size_t)n * NE + e2] * g_H[e * NE + e2];
    float quad = r * he;

    red[e] = cross; __syncthreads();
    for (int s = 32; s >= 1; s >>= 1) { if (e < s) red[e] += red[e + s]; __syncthreads(); }
    float crs = red[0]; __syncthreads();
    red[e] = quad; __syncthreads();
    for (int s = 32; s >= 1; s >>= 1) { if (e < s) red[e] += red[e + s]; __syncthreads(); }
    float qd = red[0];
    if (e == 0) {
        atomicAdd(&g_acc[0], g_qnorm[n]);
        atomicAdd(&g_acc[1], crs);
        atomicAdd(&g_acc[2], qd);
    }
}

// ---------------- out[n,i] = sum_e r * sum_k Cnew[e,i*C+k]*y[k] + pwB ----------------
__global__ void k_out(float* __restrict__ out, const float* __restrict__ pwB) {
    __shared__ float ys[CC];
    __shared__ float rr[NE];
    __shared__ int   ai[NE];
    __shared__ int   acnt;
    __shared__ float os[ROUT];
    int n = blockIdx.x;
    int tid = threadIdx.x;
    ys[tid] = g_Y[(size_t)n * CC + tid];
    if (tid < NE) rr[tid] = g_resp[(size_t)n * NE + tid];
    __syncthreads();
    if (tid == 0) {
        int c = 0;
        for (int e = 0; e < NE; e++) if (rr[e] > 1e-12f) ai[c++] = e;
        acnt = c;
    }
    __syncthreads();
    int warp = tid >> 5, lane = tid & 31;
    float acc[32];
#pragma unroll
    for (int it = 0; it < 32; it++) acc[it] = 0.f;
    int cnt = acnt;
    for (int a = 0; a < cnt; a++) {
        int e = ai[a];
        float r = rr[e];
        const float* crow = g_Cnew + (size_t)e * DD;
#pragma unroll
        for (int it = 0; it < 32; it++) {
            int i = it * 8 + warp;
            const float* p = crow + i * CC + lane;
            float s = 0.f;
#pragma unroll
            for (int m = 0; m < 8; m++) s += p[m * 32] * ys[lane + m * 32];
#pragma unroll
            for (int o = 16; o >= 1; o >>= 1) s += __shfl_xor_sync(0xffffffffu, s, o);
            acc[it] += r * s;
        }
    }
#pragma unroll
    for (int it = 0; it < 32; it++)
        if (lane == 0) os[it * 8 + warp] = acc[it];
    __syncthreads();
    out[(size_t)n * ROUT + tid] = os[tid] + pwB[tid];
}

// ---------------- final loss ----------------
__global__ void k_final(float* __restrict__ out, int out_size) {
    float loss = COMMITv * (g_acc[0] - 2.f * g_acc[1] + g_acc[2]) / ((float)NN * (float)DD);
    for (int i = NN * ROUT + threadIdx.x; i < out_size; i += blockDim.x) out[i] = loss;
}

extern "C" void kernel_launch(void* const* d_in, const int* in_sizes, int n_in,
                              void* d_out, int out_size) {
    const float* x     = (const float*)d_in[0];
    const float* u     = (const float*)d_in[1];
    const float* W     = (const float*)d_in[2];
    const float* bvec  = (const float*)d_in[3];
    const float* pw1   = (const float*)d_in[4];
    const float* pwB   = (const float*)d_in[5];
    const float* cents = (const float*)d_in[6];
    float* out = (float*)d_out;

    k_zero<<<256, 256>>>();
    k_gram<<<dim3(4, 4, 32), 256>>>(W);
    k_centW<<<128, 256>>>(W, cents, bvec);
    k_pw1T<<<CC, CC>>>(pw1);
    k_xsmall<<<256, 256>>>(x);
    k_resp<<<NN, 64>>>(u);
    k_A<<<64, 256>>>(x);
    k_cnew<<<1024, 256>>>(W, cents, bvec);
    k_H<<<128, 256>>>();
    k_loss<<<NN, 64>>>();
    k_out<<<NN, 256>>>(out, pwB);
    if (out_size > NN * ROUT) k_final<<<1, 64>>>(out, out_size);
}

// round 4
// speedup vs baseline: 3.4255x; 3.4255x over previous
#include <cuda_runtime.h>
#include <math.h>
#include <stdint.h>

#define CC 256
#define NN 2048
#define DD 65536
#define NE 64
#define ROUT 256
#define DECAYv 0.999f
#define GAMv 4.8828125e-7f
#define COMMITv 0.25f

__device__ float g_M[CC*CC];
__device__ float g_G[NE*CC];
__device__ float g_A[NE*CC];
__device__ float g_B2[NE*CC];
__device__ float g_Q[NE*NE];
__device__ float g_H[NE*NE];
__device__ float g_cnorm[NE], g_bc[NE], g_s[NE], g_t[NE];
__device__ float g_Wtb[CC];
__device__ float g_bb;
__device__ float g_acc[8];
__device__ float g_XM[NN*CC];
__device__ float g_Y[NN*CC];
__device__ float g_xG[NN*NE];
__device__ float g_xWtb[NN];
__device__ float g_resp[NN*NE];
__device__ int   g_cnt[NE];
__device__ int   g_tokn[NE*NN];
__device__ float g_tokr[NE*NN];
__device__ float g_Cnew[NE*DD];

__device__ __forceinline__ void mma8(float* c, const uint32_t* a, const uint32_t* b) {
    asm volatile("mma.sync.aligned.m16n8k8.row.col.f32.tf32.tf32.f32 "
        "{%0,%1,%2,%3}, {%4,%5,%6,%7}, {%8,%9}, {%0,%1,%2,%3};"
        : "+f"(c[0]), "+f"(c[1]), "+f"(c[2]), "+f"(c[3])
        : "r"(a[0]), "r"(a[1]), "r"(a[2]), "r"(a[3]), "r"(b[0]), "r"(b[1]));
}
__device__ __forceinline__ uint32_t fb(float x) { return __float_as_uint(x); }
__device__ __forceinline__ void hilo(float v, uint32_t& h, uint32_t& l) {
    uint32_t hb = __float_as_uint(v) & 0xFFFFE000u;
    h = hb;
    l = fb(v - __uint_as_float(hb));
}

// ---------------- zero ----------------
__global__ void k_zero(float* __restrict__ out) {
    int i = blockIdx.x * 256 + threadIdx.x;
    if (i < NN*ROUT) out[i] = 0.f;
    if (i < CC*CC) g_M[i] = 0.f;
    if (i < NE*CC) { g_G[i] = 0.f; g_A[i] = 0.f; g_B2[i] = 0.f; }
    if (i < NE*NE) { g_Q[i] = 0.f; g_H[i] = 0.f; }
    if (i < CC) g_Wtb[i] = 0.f;
    if (i < NE) { g_cnorm[i]=0.f; g_bc[i]=0.f; g_s[i]=0.f; g_t[i]=0.f; g_cnt[i]=0; }
    if (i < 8) g_acc[i] = 0.f;
    if (i == 8) g_bb = 0.f;
}

// ---------------- M = W^T W, plain tf32, splitK=32 ----------------
__global__ void __launch_bounds__(256) k_gram(const float* __restrict__ W) {
    __shared__ float Wi[32][132];
    __shared__ float Wj[32][132];
    int tid=threadIdx.x, warp=tid>>5, lane=tid&31, gid=lane>>2, tig=lane&3;
    int wm=warp>>2, wn=warp&3;
    int i0=blockIdx.x*128, j0=blockIdx.y*128, d0=blockIdx.z*2048;
    float acc[4][4][4];
#pragma unroll
    for (int mt=0;mt<4;mt++)
#pragma unroll
        for (int nt=0;nt<4;nt++)
#pragma unroll
            for (int q=0;q<4;q++) acc[mt][nt][q]=0.f;

    for (int ch=0; ch<64; ch++) {
        int drow = d0 + ch*32;
#pragma unroll
        for (int l=0;l<4;l++) {
            int idx = tid + l*256;
            int row = idx>>5, c4 = (idx&31)*4;
            float4 vi = *(const float4*)(W + (size_t)(drow+row)*CC + i0 + c4);
            Wi[row][c4]=vi.x; Wi[row][c4+1]=vi.y; Wi[row][c4+2]=vi.z; Wi[row][c4+3]=vi.w;
            float4 vj = *(const float4*)(W + (size_t)(drow+row)*CC + j0 + c4);
            Wj[row][c4]=vj.x; Wj[row][c4+1]=vj.y; Wj[row][c4+2]=vj.z; Wj[row][c4+3]=vj.w;
        }
        __syncthreads();
#pragma unroll
        for (int k8=0;k8<4;k8++) {
            int kb = k8*8;
            uint32_t a[4][4], b[4][2];
#pragma unroll
            for (int mt=0;mt<4;mt++) {
                int ib = wm*64 + mt*16 + gid;
                a[mt][0]=fb(Wi[kb+tig][ib]);   a[mt][1]=fb(Wi[kb+tig][ib+8]);
                a[mt][2]=fb(Wi[kb+tig+4][ib]); a[mt][3]=fb(Wi[kb+tig+4][ib+8]);
            }
#pragma unroll
            for (int nt=0;nt<4;nt++) {
                int jb = wn*32 + nt*8 + gid;
                b[nt][0]=fb(Wj[kb+tig][jb]); b[nt][1]=fb(Wj[kb+tig+4][jb]);
            }
#pragma unroll
            for (int mt=0;mt<4;mt++)
#pragma unroll
                for (int nt=0;nt<4;nt++) mma8(acc[mt][nt], a[mt], b[nt]);
        }
        __syncthreads();
    }
#pragma unroll
    for (int mt=0;mt<4;mt++)
#pragma unroll
        for (int nt=0;nt<4;nt++) {
            int i = i0 + wm*64 + mt*16 + gid;
            int j = j0 + wn*32 + nt*8 + 2*tig;
            atomicAdd(&g_M[i*CC+j],     acc[mt][nt][0]);
            atomicAdd(&g_M[i*CC+j+1],   acc[mt][nt][1]);
            atomicAdd(&g_M[(i+8)*CC+j], acc[mt][nt][2]);
            atomicAdd(&g_M[(i+8)*CC+j+1], acc[mt][nt][3]);
        }
}

// ---------------- G = Cents@W (tf32 hi/lo split) + Wtb/cnorm/bc/bb ----------------
__global__ void __launch_bounds__(256) k_centW(const float* __restrict__ W,
                                               const float* __restrict__ cents,
                                               const float* __restrict__ bvec) {
    __shared__ float Cs[64][36];
    __shared__ float Ws[32][260];
    __shared__ float bs[32];
    int tid=threadIdx.x, warp=tid>>5, lane=tid&31, gid=lane>>2, tig=lane&3;
    int d0 = blockIdx.x * 512;
    float acc[4][4][4];
#pragma unroll
    for (int mt=0;mt<4;mt++)
#pragma unroll
        for (int nt=0;nt<4;nt++)
#pragma unroll
            for (int q=0;q<4;q++) acc[mt][nt][q]=0.f;
    float accWtb=0.f, accCN=0.f, accBC=0.f, accBB=0.f;

    for (int ch=0; ch<16; ch++) {
        int dbase = d0 + ch*32;
#pragma unroll
        for (int l=0;l<2;l++) {
            int idx = tid + l*256;
            int e = idx>>3, q = (idx&7)*4;
            float4 v = *(const float4*)(cents + (size_t)e*DD + dbase + q);
            Cs[e][q]=v.x; Cs[e][q+1]=v.y; Cs[e][q+2]=v.z; Cs[e][q+3]=v.w;
        }
#pragma unroll
        for (int l=0;l<8;l++) {
            int idx = tid + l*256;
            int row = idx>>6, q = (idx&63)*4;
            float4 v = *(const float4*)(W + (size_t)(dbase+row)*CC + q);
            Ws[row][q]=v.x; Ws[row][q+1]=v.y; Ws[row][q+2]=v.z; Ws[row][q+3]=v.w;
        }
        if (tid < 32) bs[tid] = bvec[dbase + tid];
        __syncthreads();

        {
            float aw = 0.f;
            for (int k=0;k<32;k++) aw += bs[k]*Ws[k][tid];
            accWtb += aw;
        }
        if (tid < 64) {
            float cn=0.f, bc=0.f;
            for (int k=0;k<32;k++) { float c=Cs[tid][k]; cn+=c*c; bc+=c*bs[k]; }
            accCN += cn; accBC += bc;
        }
        if (tid == 64) {
            float sb=0.f;
            for (int k=0;k<32;k++) sb += bs[k]*bs[k];
            accBB += sb;
        }
#pragma unroll
        for (int k8=0;k8<4;k8++) {
            int kb = k8*8;
            uint32_t ah[4][4], al[4][4], bh[4][2], bl[4][2];
#pragma unroll
            for (int mt=0;mt<4;mt++) {
                int e = mt*16 + gid;
                hilo(Cs[e][kb+tig],     ah[mt][0], al[mt][0]);
                hilo(Cs[e+8][kb+tig],   ah[mt][1], al[mt][1]);
                hilo(Cs[e][kb+tig+4],   ah[mt][2], al[mt][2]);
                hilo(Cs[e+8][kb+tig+4], ah[mt][3], al[mt][3]);
            }
#pragma unroll
            for (int nt=0;nt<4;nt++) {
                int c = warp*32 + nt*8 + gid;
                hilo(Ws[kb+tig][c],   bh[nt][0], bl[nt][0]);
                hilo(Ws[kb+tig+4][c], bh[nt][1], bl[nt][1]);
            }
#pragma unroll
            for (int mt=0;mt<4;mt++)
#pragma unroll
                for (int nt=0;nt<4;nt++) {
                    mma8(acc[mt][nt], ah[mt], bh[nt]);
                    mma8(acc[mt][nt], ah[mt], bl[nt]);
                    mma8(acc[mt][nt], al[mt], bh[nt]);
                }
        }
        __syncthreads();
    }
#pragma unroll
    for (int mt=0;mt<4;mt++)
#pragma unroll
        for (int nt=0;nt<4;nt++) {
            int e = mt*16 + gid;
            int c = warp*32 + nt*8 + 2*tig;
            atomicAdd(&g_G[e*CC+c],       acc[mt][nt][0]);
            atomicAdd(&g_G[e*CC+c+1],     acc[mt][nt][1]);
            atomicAdd(&g_G[(e+8)*CC+c],   acc[mt][nt][2]);
            atomicAdd(&g_G[(e+8)*CC+c+1], acc[mt][nt][3]);
        }
    atomicAdd(&g_Wtb[tid], accWtb);
    if (tid < 64) { atomicAdd(&g_cnorm[tid], accCN); atomicAdd(&g_bc[tid], accBC); }
    if (tid == 64) atomicAdd(&g_bb, accBB);
}

// ---------------- XM / Y / xG : X @ {M, pw1, G}^T  hi/lo split ----------------
__global__ void __launch_bounds__(256) k_big(const float* __restrict__ x,
                                             const float* __restrict__ pw1) {
    __shared__ float Xs[64][36];
    __shared__ float Bs[64][36];
    int tid=threadIdx.x, warp=tid>>5, lane=tid&31, gid=lane>>2, tig=lane&3;
    int wm = warp>>2, wn = warp&3;
    int tok0 = blockIdx.x * 64;
    int by = blockIdx.y;
    const float* src = (by < 4) ? (g_M + (size_t)by*64*CC)
                     : (by < 8) ? (pw1 + (size_t)(by-4)*64*CC)
                     : g_G;
    float acc[2][2][4];
#pragma unroll
    for (int mt=0;mt<2;mt++)
#pragma unroll
        for (int nt=0;nt<2;nt++)
#pragma unroll
            for (int q=0;q<4;q++) acc[mt][nt][q]=0.f;

    for (int ch=0; ch<8; ch++) {
        int kc = ch*32;
#pragma unroll
        for (int l=0;l<2;l++) {
            int idx = tid + l*256;
            int row = idx>>3, q = (idx&7)*4;
            float4 v = *(const float4*)(x + (size_t)(tok0+row)*CC + kc + q);
            Xs[row][q]=v.x; Xs[row][q+1]=v.y; Xs[row][q+2]=v.z; Xs[row][q+3]=v.w;
            float4 w = *(const float4*)(src + (size_t)row*CC + kc + q);
            Bs[row][q]=w.x; Bs[row][q+1]=w.y; Bs[row][q+2]=w.z; Bs[row][q+3]=w.w;
        }
        __syncthreads();
#pragma unroll
        for (int k8=0;k8<4;k8++) {
            int kb = k8*8;
            uint32_t ah[2][4], al[2][4], bh[2][2], bl[2][2];
#pragma unroll
            for (int mt=0;mt<2;mt++) {
                int m0 = wm*32 + mt*16 + gid;
                hilo(Xs[m0][kb+tig],     ah[mt][0], al[mt][0]);
                hilo(Xs[m0+8][kb+tig],   ah[mt][1], al[mt][1]);
                hilo(Xs[m0][kb+tig+4],   ah[mt][2], al[mt][2]);
                hilo(Xs[m0+8][kb+tig+4], ah[mt][3], al[mt][3]);
            }
#pragma unroll
            for (int nt=0;nt<2;nt++) {
                int nl = wn*16 + nt*8 + gid;
                hilo(Bs[nl][kb+tig],   bh[nt][0], bl[nt][0]);
                hilo(Bs[nl][kb+tig+4], bh[nt][1], bl[nt][1]);
            }
#pragma unroll
            for (int mt=0;mt<2;mt++)
#pragma unroll
                for (int nt=0;nt<2;nt++) {
                    mma8(acc[mt][nt], ah[mt], bh[nt]);
                    mma8(acc[mt][nt], ah[mt], bl[nt]);
                    mma8(acc[mt][nt], al[mt], bh[nt]);
                }
        }
        __syncthreads();
    }
#pragma unroll
    for (int mt=0;mt<2;mt++)
#pragma unroll
        for (int nt=0;nt<2;nt++) {
            int col = wn*16 + nt*8 + 2*tig;
#pragma unroll
            for (int rr=0;rr<2;rr++) {
                int tok = tok0 + wm*32 + mt*16 + gid + rr*8;
                float v0 = acc[mt][nt][rr*2], v1 = acc[mt][nt][rr*2+1];
                if (by < 4) {
                    g_XM[(size_t)tok*CC + by*64 + col] = v0;
                    g_XM[(size_t)tok*CC + by*64 + col+1] = v1;
                } else if (by < 8) {
                    g_Y[(size_t)tok*CC + (by-4)*64 + col] = v0;
                    g_Y[(size_t)tok*CC + (by-4)*64 + col+1] = v1;
                } else {
                    g_xG[(size_t)tok*NE + col] = v0;
                    g_xG[(size_t)tok*NE + col+1] = v1;
                }
            }
        }
}

// ---------------- per-token xWtb + S0 ----------------
__global__ void k_xw(const float* __restrict__ x) {
    int warp = threadIdx.x>>5, lane = threadIdx.x&31;
    int n = blockIdx.x*8 + warp;
    float qd=0.f, xw=0.f;
#pragma unroll
    for (int m=0;m<8;m++) {
        int idx = lane + m*32;
        float xv = x[(size_t)n*CC+idx];
        qd += xv * g_XM[(size_t)n*CC+idx];
        xw += xv * g_Wtb[idx];
    }
#pragma unroll
    for (int o=16;o>=1;o>>=1) {
        qd += __shfl_xor_sync(0xffffffffu, qd, o);
        xw += __shfl_xor_sync(0xffffffffu, xw, o);
    }
    if (lane == 0) {
        g_xWtb[n] = xw;
        atomicAdd(&g_acc[0], qd + 2.f*xw + g_bb);
    }
}

// ---------------- resp + S1a + binning ----------------
__global__ void k_resp(const float* __restrict__ u) {
    __shared__ float red[64];
    int n = blockIdx.x, e = threadIdx.x;
    float xg = g_xG[(size_t)n*NE+e] + g_bc[e];
    float d2 = g_cnorm[e] - 2.f*xg;
    float g = -logf(-logf(u[(size_t)n*NE+e]));
    float logit = g - d2;
    red[e] = logit; __syncthreads();
    for (int s=32;s>=1;s>>=1) { if (e<s) red[e]=fmaxf(red[e],red[e+s]); __syncthreads(); }
    float mx = red[0]; __syncthreads();
    float ex = expf(logit - mx);
    red[e] = ex; __syncthreads();
    for (int s=32;s>=1;s>>=1) { if (e<s) red[e]+=red[e+s]; __syncthreads(); }
    float r = ex / red[0];
    __syncthreads();
    g_resp[(size_t)n*NE+e] = r;
    red[e] = r * xg; __syncthreads();
    for (int s=32;s>=1;s>>=1) { if (e<s) red[e]+=red[e+s]; __syncthreads(); }
    if (e == 0) atomicAdd(&g_acc[1], red[0]);
    if (r > 1e-9f) {
        int p = atomicAdd(&g_cnt[e], 1);
        g_tokn[e*NN+p] = n;
        g_tokr[e*NN+p] = r;
    }
}

// ---------------- A=R^T X, B2=R^T XM, Q=R^T R, s, t (tf32) ----------------
__global__ void __launch_bounds__(256) k_RX(const float* __restrict__ x) {
    __shared__ float Rs[32][68];
    __shared__ float Xs[32][260];
    __shared__ float Ms[32][260];
    __shared__ float tw[32];
    int tid=threadIdx.x, warp=tid>>5, lane=tid&31, gid=lane>>2, tig=lane&3;
    int n0 = blockIdx.x * 128;
    float accA[4][4][4], accB[4][4][4], accQ[4][4];
#pragma unroll
    for (int mt=0;mt<4;mt++) {
#pragma unroll
        for (int nt=0;nt<4;nt++)
#pragma unroll
            for (int q=0;q<4;q++) { accA[mt][nt][q]=0.f; accB[mt][nt][q]=0.f; }
#pragma unroll
        for (int q=0;q<4;q++) accQ[mt][q]=0.f;
    }
    float sp=0.f, tp=0.f;

    for (int cchunk=0; cchunk<4; cchunk++) {
        int nb = n0 + cchunk*32;
#pragma unroll
        for (int l=0;l<8;l++) {
            int idx = tid + l*256;
            int row = idx>>6, e2 = idx&63;
            Rs[row][e2] = g_resp[(size_t)(nb+row)*NE + e2];
        }
#pragma unroll
        for (int l=0;l<8;l++) {
            int idx = tid + l*256;
            int row = idx>>6, q = (idx&63)*4;
            float4 v = *(const float4*)(x + (size_t)(nb+row)*CC + q);
            Xs[row][q]=v.x; Xs[row][q+1]=v.y; Xs[row][q+2]=v.z; Xs[row][q+3]=v.w;
            float4 w = *(const float4*)(g_XM + (size_t)(nb+row)*CC + q);
            Ms[row][q]=w.x; Ms[row][q+1]=w.y; Ms[row][q+2]=w.z; Ms[row][q+3]=w.w;
        }
        if (tid < 32) tw[tid] = g_xWtb[nb+tid];
        __syncthreads();
        if (tid < 64) {
            for (int k=0;k<32;k++) { float rv = Rs[k][tid]; sp += rv; tp += rv*tw[k]; }
        }
#pragma unroll
        for (int k8=0;k8<4;k8++) {
            int kb = k8*8;
            uint32_t am[4][4];
#pragma unroll
            for (int mt=0;mt<4;mt++) {
                int m0 = mt*16;
                am[mt][0]=fb(Rs[kb+tig][m0+gid]);   am[mt][1]=fb(Rs[kb+tig][m0+gid+8]);
                am[mt][2]=fb(Rs[kb+tig+4][m0+gid]); am[mt][3]=fb(Rs[kb+tig+4][m0+gid+8]);
            }
#pragma unroll
            for (int nt=0;nt<4;nt++) {
                int c = warp*32 + nt*8 + gid;
                uint32_t bx[2] = { fb(Xs[kb+tig][c]), fb(Xs[kb+tig+4][c]) };
                uint32_t bm[2] = { fb(Ms[kb+tig][c]), fb(Ms[kb+tig+4][c]) };
#pragma unroll
                for (int mt=0;mt<4;mt++) { mma8(accA[mt][nt], am[mt], bx); mma8(accB[mt][nt], am[mt], bm); }
            }
            {
                int eq = warp*8 + gid;
                uint32_t bq[2] = { fb(Rs[kb+tig][eq]), fb(Rs[kb+tig+4][eq]) };
#pragma unroll
                for (int mt=0;mt<4;mt++) mma8(accQ[mt], am[mt], bq);
            }
        }
        __syncthreads();
    }
#pragma unroll
    for (int mt=0;mt<4;mt++) {
#pragma unroll
        for (int nt=0;nt<4;nt++) {
            int e = mt*16 + gid;
            int c = warp*32 + nt*8 + 2*tig;
            atomicAdd(&g_A[e*CC+c],       accA[mt][nt][0]);
            atomicAdd(&g_A[e*CC+c+1],     accA[mt][nt][1]);
            atomicAdd(&g_A[(e+8)*CC+c],   accA[mt][nt][2]);
            atomicAdd(&g_A[(e+8)*CC+c+1], accA[mt][nt][3]);
            atomicAdd(&g_B2[e*CC+c],       accB[mt][nt][0]);
            atomicAdd(&g_B2[e*CC+c+1],     accB[mt][nt][1]);
            atomicAdd(&g_B2[(e+8)*CC+c],   accB[mt][nt][2]);
            atomicAdd(&g_B2[(e+8)*CC+c+1], accB[mt][nt][3]);
        }
        int e = mt*16 + gid;
        int eq = warp*8 + 2*tig;
        atomicAdd(&g_Q[e*NE+eq],       accQ[mt][0]);
        atomicAdd(&g_Q[e*NE+eq+1],     accQ[mt][1]);
        atomicAdd(&g_Q[(e+8)*NE+eq],   accQ[mt][2]);
        atomicAdd(&g_Q[(e+8)*NE+eq+1], accQ[mt][3]);
    }
    if (tid < 64) { atomicAdd(&g_s[tid], sp); atomicAdd(&g_t[tid], tp); }
}

// ---------------- Cnew = decay*Cents + gam*(A@W^T + s b^T)  (tf32) ----------------
__global__ void __launch_bounds__(256) k_cnew(const float* __restrict__ W,
                                              const float* __restrict__ cents,
                                              const float* __restrict__ bvec) {
    __shared__ float As[64][36];
    __shared__ float Ws[128][36];
    __shared__ float ss[64];
    int tid=threadIdx.x, warp=tid>>5, lane=tid&31, gid=lane>>2, tig=lane&3;
    int d0 = blockIdx.x * 128;
    if (tid < 64) ss[tid] = g_s[tid];
    float acc[4][2][4];
#pragma unroll
    for (int mt=0;mt<4;mt++)
#pragma unroll
        for (int nt=0;nt<2;nt++)
#pragma unroll
            for (int q=0;q<4;q++) acc[mt][nt][q]=0.f;

    for (int ch=0; ch<8; ch++) {
        int kc = ch*32;
#pragma unroll
        for (int l=0;l<2;l++) {
            int idx = tid + l*256;
            int row = idx>>3, q = (idx&7)*4;
            float4 v = *(const float4*)(g_A + (size_t)row*CC + kc + q);
            As[row][q]=v.x; As[row][q+1]=v.y; As[row][q+2]=v.z; As[row][q+3]=v.w;
        }
#pragma unroll
        for (int l=0;l<4;l++) {
            int idx = tid + l*256;
            int row = idx>>3, q = (idx&7)*4;
            float4 v = *(const float4*)(W + (size_t)(d0+row)*CC + kc + q);
            Ws[row][q]=v.x; Ws[row][q+1]=v.y; Ws[row][q+2]=v.z; Ws[row][q+3]=v.w;
        }
        __syncthreads();
#pragma unroll
        for (int k8=0;k8<4;k8++) {
            int kb = k8*8;
            uint32_t a[4][4], b[2][2];
#pragma unroll
            for (int mt=0;mt<4;mt++) {
                int e = mt*16 + gid;
                a[mt][0]=fb(As[e][kb+tig]);   a[mt][1]=fb(As[e+8][kb+tig]);
                a[mt][2]=fb(As[e][kb+tig+4]); a[mt][3]=fb(As[e+8][kb+tig+4]);
            }
#pragma unroll
            for (int nt=0;nt<2;nt++) {
                int dl = warp*16 + nt*8 + gid;
                b[nt][0]=fb(Ws[dl][kb+tig]); b[nt][1]=fb(Ws[dl][kb+tig+4]);
            }
#pragma unroll
            for (int mt=0;mt<4;mt++)
#pragma unroll
                for (int nt=0;nt<2;nt++) mma8(acc[mt][nt], a[mt], b[nt]);
        }
        __syncthreads();
    }
#pragma unroll
    for (int mt=0;mt<4;mt++)
#pragma unroll
        for (int nt=0;nt<2;nt++) {
            int e = mt*16 + gid;
            int d = d0 + warp*16 + nt*8 + 2*tig;
            float b0 = bvec[d], b1 = bvec[d+1];
            g_Cnew[(size_t)e*DD+d]       = DECAYv*cents[(size_t)e*DD+d]       + GAMv*(acc[mt][nt][0] + ss[e]*b0);
            g_Cnew[(size_t)e*DD+d+1]     = DECAYv*cents[(size_t)e*DD+d+1]     + GAMv*(acc[mt][nt][1] + ss[e]*b1);
            g_Cnew[(size_t)(e+8)*DD+d]   = DECAYv*cents[(size_t)(e+8)*DD+d]   + GAMv*(acc[mt][nt][2] + ss[e+8]*b0);
            g_Cnew[(size_t)(e+8)*DD+d+1] = DECAYv*cents[(size_t)(e+8)*DD+d+1] + GAMv*(acc[mt][nt][3] + ss[e+8]*b1);
        }
}

// ---------------- H = Cnew Cnew^T (tf32, splitK) ----------------
__global__ void __launch_bounds__(256) k_H() {
    __shared__ float Cs[64][36];
    int tid=threadIdx.x, warp=tid>>5, lane=tid&31, gid=lane>>2, tig=lane&3;
    int d0 = blockIdx.x * 512;
    float acc[4][4];
#pragma unroll
    for (int mt=0;mt<4;mt++)
#pragma unroll
        for (int q=0;q<4;q++) acc[mt][q]=0.f;

    for (int ch=0; ch<16; ch++) {
        int dbase = d0 + ch*32;
#pragma unroll
        for (int l=0;l<2;l++) {
            int idx = tid + l*256;
            int e = idx>>3, q = (idx&7)*4;
            float4 v = *(const float4*)(g_Cnew + (size_t)e*DD + dbase + q);
            Cs[e][q]=v.x; Cs[e][q+1]=v.y; Cs[e][q+2]=v.z; Cs[e][q+3]=v.w;
        }
        __syncthreads();
#pragma unroll
        for (int k8=0;k8<4;k8++) {
            int kb = k8*8;
            uint32_t a[4][4], b[2];
#pragma unroll
            for (int mt=0;mt<4;mt++) {
                int e = mt*16 + gid;
                a[mt][0]=fb(Cs[e][kb+tig]);   a[mt][1]=fb(Cs[e+8][kb+tig]);
                a[mt][2]=fb(Cs[e][kb+tig+4]); a[mt][3]=fb(Cs[e+8][kb+tig+4]);
            }
            int n0 = warp*8 + gid;
            b[0]=fb(Cs[n0][kb+tig]); b[1]=fb(Cs[n0][kb+tig+4]);
#pragma unroll
            for (int mt=0;mt<4;mt++) mma8(acc[mt], a[mt], b);
        }
        __syncthreads();
    }
#pragma unroll
    for (int mt=0;mt<4;mt++) {
        int e = mt*16 + gid;
        int n = warp*8 + 2*tig;
        atomicAdd(&g_H[e*NE+n],       acc[mt][0]);
        atomicAdd(&g_H[e*NE+n+1],     acc[mt][1]);
        atomicAdd(&g_H[(e+8)*NE+n],   acc[mt][2]);
        atomicAdd(&g_H[(e+8)*NE+n+1], acc[mt][3]);
    }
}

// ---------------- final loss scalar ----------------
__global__ void k_lossfin() {
    __shared__ float red[256];
    int tid = threadIdx.x;
    float p = 0.f;
    for (int idx = tid; idx < NE*CC; idx += 256) {
        int e = idx >> 8, c = idx & 255;
        p += g_A[idx] * (g_B2[idx] + g_s[e]*g_Wtb[c]);
    }
    if (tid < NE) p += g_s[tid]*(g_t[tid] + g_bb*g_s[tid]);
    float q = 0.f;
    for (int idx = tid; idx < NE*NE; idx += 256) q += g_H[idx]*g_Q[idx];
    red[tid] = p; __syncthreads();
    for (int s=128;s>=1;s>>=1) { if (tid<s) red[tid]+=red[tid+s]; __syncthreads(); }
    float psum = red[0]; __syncthreads();
    red[tid] = q; __syncthreads();
    for (int s=128;s>=1;s>>=1) { if (tid<s) red[tid]+=red[tid+s]; __syncthreads(); }
    if (tid == 0) {
        float S1 = DECAYv*g_acc[1] + GAMv*psum;
        g_acc[7] = COMMITv * (g_acc[0] - 2.f*S1 + red[0]) / ((float)NN * (float)DD);
    }
}

// ---------------- binned output gather-GEMM (hi/lo split) ----------------
__global__ void __launch_bounds__(256) k_out(float* __restrict__ out) {
    __shared__ float ys[32][260];
    __shared__ float Cw[256][36];
    __shared__ int   stok[32];
    int e = blockIdx.y;
    int cnt = g_cnt[e];
    int a0 = blockIdx.x * 32;
    if (a0 >= cnt) return;
    int tid=threadIdx.x, warp=tid>>5, lane=tid&31, gid=lane>>2, tig=lane&3;
    int wm = warp>>2, wn = warp&3;
#pragma unroll
    for (int l=0;l<8;l++) {
        int idx = tid + l*256;
        int row = idx >> 6, q = idx & 63;
        int aa = a0 + row;
        float r = 0.f; int n = 0;
        float4 v = make_float4(0.f,0.f,0.f,0.f);
        if (aa < cnt) {
            n = g_tokn[e*NN+aa]; r = g_tokr[e*NN+aa];
            v = *(const float4*)(g_Y + (size_t)n*CC + q*4);
        }
        ys[row][q*4]=r*v.x; ys[row][q*4+1]=r*v.y; ys[row][q*4+2]=r*v.z; ys[row][q*4+3]=r*v.w;
        if (q == 0) stok[row] = n;
    }
    __syncthreads();
    float acc[8][4];
#pragma unroll
    for (int nt=0;nt<8;nt++)
#pragma unroll
        for (int q=0;q<4;q++) acc[nt][q]=0.f;

    for (int ch=0; ch<8; ch++) {
        int kc = ch*32;
#pragma unroll
        for (int l=0;l<8;l++) {
            int idx = tid + l*256;
            int row = idx >> 3, q = (idx & 7)*4;
            float4 v = *(const float4*)(g_Cnew + (size_t)e*DD + (size_t)row*CC + kc + q);
            Cw[row][q]=v.x; Cw[row][q+1]=v.y; Cw[row][q+2]=v.z; Cw[row][q+3]=v.w;
        }
        __syncthreads();
#pragma unroll
        for (int k8=0;k8<4;k8++) {
            int kb = k8*8;
            uint32_t ah[4], al[4];
            int m0 = wm*16 + gid;
            hilo(ys[m0][kc+kb+tig],     ah[0], al[0]);
            hilo(ys[m0+8][kc+kb+tig],   ah[1], al[1]);
            hilo(ys[m0][kc+kb+tig+4],   ah[2], al[2]);
            hilo(ys[m0+8][kc+kb+tig+4], ah[3], al[3]);
#pragma unroll
            for (int nt=0;nt<8;nt++) {
                int nc = wn*64 + nt*8 + gid;
                uint32_t bh[2], bl[2];
                hilo(Cw[nc][kb+tig],   bh[0], bl[0]);
                hilo(Cw[nc][kb+tig+4], bh[1], bl[1]);
                mma8(acc[nt], ah, bh);
                mma8(acc[nt], ah, bl);
                mma8(acc[nt], al, bh);
            }
        }
        __syncthreads();
    }
    int t0 = wm*16 + gid;
    int r0 = stok[t0], r1 = stok[t0+8];
#pragma unroll
    for (int nt=0;nt<8;nt++) {
        int i = wn*64 + nt*8 + 2*tig;
        atomicAdd(out + (size_t)r0*ROUT + i,   acc[nt][0]);
        atomicAdd(out + (size_t)r0*ROUT + i+1, acc[nt][1]);
        atomicAdd(out + (size_t)r1*ROUT + i,   acc[nt][2]);
        atomicAdd(out + (size_t)r1*ROUT + i+1, acc[nt][3]);
    }
}

// ---------------- bias + loss tail ----------------
__global__ void k_final(float* __restrict__ out, const float* __restrict__ pwB, int out_size) {
    int b = blockIdx.x, tid = threadIdx.x;
    if (b < NN) {
        out[(size_t)b*ROUT + tid] += pwB[tid];
    } else {
        for (int i = NN*ROUT + tid; i < out_size; i += 256) out[i] = g_acc[7];
    }
}

extern "C" void kernel_launch(void* const* d_in, const int* in_sizes, int n_in,
                              void* d_out, int out_size) {
    const float* x     = (const float*)d_in[0];
    const float* u     = (const float*)d_in[1];
    const float* W     = (const float*)d_in[2];
    const float* bvec  = (const float*)d_in[3];
    const float* pw1   = (const float*)d_in[4];
    const float* pwB   = (const float*)d_in[5];
    const float* cents = (const float*)d_in[6];
    float* out = (float*)d_out;

    k_zero<<<2048, 256>>>(out);
    k_gram<<<dim3(2, 2, 32), 256>>>(W);
    k_centW<<<128, 256>>>(W, cents, bvec);
    k_big<<<dim3(32, 9), 256>>>(x, pw1);
    k_xw<<<256, 256>>>(x);
    k_resp<<<NN, 64>>>(u);
    k_RX<<<16, 256>>>(x);
    k_cnew<<<512, 256>>>(W, cents, bvec);
    k_H<<<128, 256>>>();
    k_lossfin<<<1, 256>>>();
    k_out<<<dim3(64, 64), 256>>>(out);
    k_final<<<NN + 1, 256>>>(out, pwB, out_size);
}

// round 5
// speedup vs baseline: 3.6991x; 1.0799x over previous
#include <cuda_runtime.h>
#include <math.h>
#include <stdint.h>

#define CC 256
#define NN 2048
#define DD 65536
#define NE 64
#define ROUT 256
#define DECAYv 0.999f
#define GAMv 4.8828125e-7f
#define COMMITv 0.25f

__device__ float g_M[CC*CC];
__device__ float g_G[NE*CC];
__device__ float g_A[NE*CC];
__device__ float g_B2[NE*CC];
__device__ float g_Q[NE*NE];
__device__ float g_H[NE*NE];
__device__ double g_cnormd[NE], g_bcd[NE], g_bbd;
__device__ float g_s[NE], g_t[NE];
__device__ float g_Wtb[CC];
__device__ double g_accd[2];      // 0: sum qnorm (S0), 1: S1a = sum r*xg
__device__ float g_XM[NN*CC];
__device__ float g_Y[NN*CC];
__device__ float g_xG[NN*NE];
__device__ float g_xWtb[NN];
__device__ float g_resp[NN*NE];
__device__ int   g_cnt[NE];
__device__ int   g_tokn[NE*NN];
__device__ float g_tokr[NE*NN];
__device__ float g_Cnew[NE*DD];

__device__ __forceinline__ void mma8(float* c, const uint32_t* a, const uint32_t* b) {
    asm volatile("mma.sync.aligned.m16n8k8.row.col.f32.tf32.tf32.f32 "
        "{%0,%1,%2,%3}, {%4,%5,%6,%7}, {%8,%9}, {%0,%1,%2,%3};"
        : "+f"(c[0]), "+f"(c[1]), "+f"(c[2]), "+f"(c[3])
        : "r"(a[0]), "r"(a[1]), "r"(a[2]), "r"(a[3]), "r"(b[0]), "r"(b[1]));
}
__device__ __forceinline__ uint32_t fb(float x) { return __float_as_uint(x); }
__device__ __forceinline__ void hilo(float v, uint32_t& h, uint32_t& l) {
    uint32_t hb = __float_as_uint(v) & 0xFFFFE000u;
    h = hb;
    l = fb(v - __uint_as_float(hb));
}

// ================= zero =================
__global__ void k_zero(float* __restrict__ out) {
    int i = blockIdx.x * 256 + threadIdx.x;
    if (i < NN*ROUT) out[i] = 0.f;
    if (i < CC*CC) g_M[i] = 0.f;
    if (i < NE*CC) { g_G[i]=0.f; g_A[i]=0.f; g_B2[i]=0.f; }
    if (i < NE*NE) { g_Q[i]=0.f; g_H[i]=0.f; }
    if (i < CC) g_Wtb[i] = 0.f;
    if (i < NE) { g_cnormd[i]=0.0; g_bcd[i]=0.0; g_s[i]=0.f; g_t[i]=0.f; g_cnt[i]=0; }
    if (i < 2) g_accd[i] = 0.0;
    if (i == 2) g_bbd = 0.0;
}

// ================= phase 1: gram | centW | Y  (merged, co-scheduled) =================
__global__ void __launch_bounds__(256) k_p1(const float* __restrict__ W,
                                            const float* __restrict__ cents,
                                            const float* __restrict__ bvec,
                                            const float* __restrict__ x,
                                            const float* __restrict__ pw1) {
    __shared__ __align__(16) char smp[43008];
    int b = blockIdx.x;
    int tid=threadIdx.x, warp=tid>>5, lane=tid&31, gid=lane>>2, tig=lane&3;

    if (b < 64) {
        // ---- gram: M = W^T W, block = 128 rows x 256 cols, splitK 32 ----
        float (*Ws)[260] = (float (*)[260])smp;
        int wm = warp>>2, wn = warp&3;
        int i0 = (b & 1) * 128;
        int d0 = (b >> 1) * 2048;
        float acc[4][8][4];
#pragma unroll
        for (int mt=0;mt<4;mt++)
#pragma unroll
            for (int nt=0;nt<8;nt++)
#pragma unroll
                for (int q=0;q<4;q++) acc[mt][nt][q]=0.f;

        for (int ch=0; ch<64; ch++) {
            int drow = d0 + ch*32;
#pragma unroll
            for (int l=0;l<8;l++) {
                int idx = tid + l*256;
                int row = idx>>6, c4 = (idx&63)*4;
                float4 v = *(const float4*)(W + (size_t)(drow+row)*CC + c4);
                Ws[row][c4]=v.x; Ws[row][c4+1]=v.y; Ws[row][c4+2]=v.z; Ws[row][c4+3]=v.w;
            }
            __syncthreads();
#pragma unroll
            for (int k8=0;k8<4;k8++) {
                int kb = k8*8;
                uint32_t a[4][4];
#pragma unroll
                for (int mt=0;mt<4;mt++) {
                    int ib = i0 + wm*64 + mt*16 + gid;
                    a[mt][0]=fb(Ws[kb+tig][ib]);   a[mt][1]=fb(Ws[kb+tig][ib+8]);
                    a[mt][2]=fb(Ws[kb+tig+4][ib]); a[mt][3]=fb(Ws[kb+tig+4][ib+8]);
                }
#pragma unroll
                for (int nt=0;nt<8;nt++) {
                    int jb = wn*64 + nt*8 + gid;
                    uint32_t bv[2] = { fb(Ws[kb+tig][jb]), fb(Ws[kb+tig+4][jb]) };
#pragma unroll
                    for (int mt=0;mt<4;mt++) mma8(acc[mt][nt], a[mt], bv);
                }
            }
            __syncthreads();
        }
#pragma unroll
        for (int mt=0;mt<4;mt++)
#pragma unroll
            for (int nt=0;nt<8;nt++) {
                int i = i0 + wm*64 + mt*16 + gid;
                int j = wn*64 + nt*8 + 2*tig;
                atomicAdd(&g_M[i*CC+j],       acc[mt][nt][0]);
                atomicAdd(&g_M[i*CC+j+1],     acc[mt][nt][1]);
                atomicAdd(&g_M[(i+8)*CC+j],   acc[mt][nt][2]);
                atomicAdd(&g_M[(i+8)*CC+j+1], acc[mt][nt][3]);
            }
    } else if (b < 192) {
        // ---- centW: G = Cents@W (hi/lo) + cnorm/bc/Wtb/bb ----
        float (*Cs)[36]  = (float (*)[36])smp;
        float (*Ws)[260] = (float (*)[260])(smp + 9216);
        float* bs        = (float*)(smp + 9216 + 33280);
        int blk = b - 64;
        int d0 = blk * 512;
        float acc[4][4][4];
#pragma unroll
        for (int mt=0;mt<4;mt++)
#pragma unroll
            for (int nt=0;nt<4;nt++)
#pragma unroll
                for (int q=0;q<4;q++) acc[mt][nt][q]=0.f;
        float accWtb=0.f, accCN=0.f, accBC=0.f, accBB=0.f;

        for (int ch=0; ch<16; ch++) {
            int dbase = d0 + ch*32;
#pragma unroll
            for (int l=0;l<2;l++) {
                int idx = tid + l*256;
                int e = idx>>3, q = (idx&7)*4;
                float4 v = *(const float4*)(cents + (size_t)e*DD + dbase + q);
                Cs[e][q]=v.x; Cs[e][q+1]=v.y; Cs[e][q+2]=v.z; Cs[e][q+3]=v.w;
            }
#pragma unroll
            for (int l=0;l<8;l++) {
                int idx = tid + l*256;
                int row = idx>>6, q = (idx&63)*4;
                float4 v = *(const float4*)(W + (size_t)(dbase+row)*CC + q);
                Ws[row][q]=v.x; Ws[row][q+1]=v.y; Ws[row][q+2]=v.z; Ws[row][q+3]=v.w;
            }
            if (tid < 32) bs[tid] = bvec[dbase + tid];
            __syncthreads();
            {
                float aw = 0.f;
                for (int k=0;k<32;k++) aw += bs[k]*Ws[k][tid];
                accWtb += aw;
            }
            if (tid < 64) {
                float cn=0.f, bc=0.f;
                for (int k=0;k<32;k++) { float c=Cs[tid][k]; cn+=c*c; bc+=c*bs[k]; }
                accCN += cn; accBC += bc;
            }
            if (tid == 64) {
                float sb=0.f;
                for (int k=0;k<32;k++) sb += bs[k]*bs[k];
                accBB += sb;
            }
#pragma unroll
            for (int k8=0;k8<4;k8++) {
                int kb = k8*8;
                uint32_t ah[4][4], al[4][4], bh[4][2], bl[4][2];
#pragma unroll
                for (int mt=0;mt<4;mt++) {
                    int e = mt*16 + gid;
                    hilo(Cs[e][kb+tig],     ah[mt][0], al[mt][0]);
                    hilo(Cs[e+8][kb+tig],   ah[mt][1], al[mt][1]);
                    hilo(Cs[e][kb+tig+4],   ah[mt][2], al[mt][2]);
                    hilo(Cs[e+8][kb+tig+4], ah[mt][3], al[mt][3]);
                }
#pragma unroll
                for (int nt=0;nt<4;nt++) {
                    int c = warp*32 + nt*8 + gid;
                    hilo(Ws[kb+tig][c],   bh[nt][0], bl[nt][0]);
                    hilo(Ws[kb+tig+4][c], bh[nt][1], bl[nt][1]);
                }
#pragma unroll
                for (int mt=0;mt<4;mt++)
#pragma unroll
                    for (int nt=0;nt<4;nt++) {
                        mma8(acc[mt][nt], ah[mt], bh[nt]);
                        mma8(acc[mt][nt], ah[mt], bl[nt]);
                        mma8(acc[mt][nt], al[mt], bh[nt]);
                    }
            }
            __syncthreads();
        }
#pragma unroll
        for (int mt=0;mt<4;mt++)
#pragma unroll
            for (int nt=0;nt<4;nt++) {
                int e = mt*16 + gid;
                int c = warp*32 + nt*8 + 2*tig;
                atomicAdd(&g_G[e*CC+c],       acc[mt][nt][0]);
                atomicAdd(&g_G[e*CC+c+1],     acc[mt][nt][1]);
                atomicAdd(&g_G[(e+8)*CC+c],   acc[mt][nt][2]);
                atomicAdd(&g_G[(e+8)*CC+c+1], acc[mt][nt][3]);
            }
        atomicAdd(&g_Wtb[tid], accWtb);
        if (tid < 64) { atomicAdd(&g_cnormd[tid], (double)accCN); atomicAdd(&g_bcd[tid], (double)accBC); }
        if (tid == 64) atomicAdd(&g_bbd, (double)accBB);
    } else {
        // ---- Y = X @ pw1^T  (hi/lo) ----
        float (*Xs)[36] = (float (*)[36])smp;
        float (*Bs)[36] = (float (*)[36])(smp + 9216);
        int yb = b - 192;
        int tok0 = (yb >> 2) * 64;
        int colgrp = yb & 3;
        const float* src = pw1 + (size_t)colgrp * 64 * CC;
        int wm = warp>>2, wn = warp&3;
        float acc[2][2][4];
#pragma unroll
        for (int mt=0;mt<2;mt++)
#pragma unroll
            for (int nt=0;nt<2;nt++)
#pragma unroll
                for (int q=0;q<4;q++) acc[mt][nt][q]=0.f;

        for (int ch=0; ch<8; ch++) {
            int kc = ch*32;
#pragma unroll
            for (int l=0;l<2;l++) {
                int idx = tid + l*256;
                int row = idx>>3, q = (idx&7)*4;
                float4 v = *(const float4*)(x + (size_t)(tok0+row)*CC + kc + q);
                Xs[row][q]=v.x; Xs[row][q+1]=v.y; Xs[row][q+2]=v.z; Xs[row][q+3]=v.w;
                float4 w = *(const float4*)(src + (size_t)row*CC + kc + q);
                Bs[row][q]=w.x; Bs[row][q+1]=w.y; Bs[row][q+2]=w.z; Bs[row][q+3]=w.w;
            }
            __syncthreads();
#pragma unroll
            for (int k8=0;k8<4;k8++) {
                int kb = k8*8;
                uint32_t ah[2][4], al[2][4], bh[2][2], bl[2][2];
#pragma unroll
                for (int mt=0;mt<2;mt++) {
                    int m0 = wm*32 + mt*16 + gid;
                    hilo(Xs[m0][kb+tig],     ah[mt][0], al[mt][0]);
                    hilo(Xs[m0+8][kb+tig],   ah[mt][1], al[mt][1]);
                    hilo(Xs[m0][kb+tig+4],   ah[mt][2], al[mt][2]);
                    hilo(Xs[m0+8][kb+tig+4], ah[mt][3], al[mt][3]);
                }
#pragma unroll
                for (int nt=0;nt<2;nt++) {
                    int nl = wn*16 + nt*8 + gid;
                    hilo(Bs[nl][kb+tig],   bh[nt][0], bl[nt][0]);
                    hilo(Bs[nl][kb+tig+4], bh[nt][1], bl[nt][1]);
                }
#pragma unroll
                for (int mt=0;mt<2;mt++)
#pragma unroll
                    for (int nt=0;nt<2;nt++) {
                        mma8(acc[mt][nt], ah[mt], bh[nt]);
                        mma8(acc[mt][nt], ah[mt], bl[nt]);
                        mma8(acc[mt][nt], al[mt], bh[nt]);
                    }
            }
            __syncthreads();
        }
#pragma unroll
        for (int mt=0;mt<2;mt++)
#pragma unroll
            for (int nt=0;nt<2;nt++) {
                int col = colgrp*64 + wn*16 + nt*8 + 2*tig;
#pragma unroll
                for (int rr=0;rr<2;rr++) {
                    int tok = tok0 + wm*32 + mt*16 + gid + rr*8;
                    g_Y[(size_t)tok*CC + col]   = acc[mt][nt][rr*2];
                    g_Y[(size_t)tok*CC + col+1] = acc[mt][nt][rr*2+1];
                }
            }
    }
}

// ================= phase 2: XM = X@M | xG = X@G^T  (hi/lo) =================
__global__ void __launch_bounds__(256) k_big2(const float* __restrict__ x) {
    __shared__ __align__(16) char smp[18432];
    float (*Xs)[36] = (float (*)[36])smp;
    float (*Bs)[36] = (float (*)[36])(smp + 9216);
    int b = blockIdx.x;
    int tid=threadIdx.x, warp=tid>>5, lane=tid&31, gid=lane>>2, tig=lane&3;
    int wm = warp>>2, wn = warp&3;
    int tok0, colgrp, mode;
    const float* src;
    if (b < 128) { tok0 = (b>>2)*64; colgrp = b&3; src = g_M + (size_t)colgrp*64*CC; mode=0; }
    else         { tok0 = (b-128)*64; colgrp = 0;  src = g_G; mode=1; }
    float acc[2][2][4];
#pragma unroll
    for (int mt=0;mt<2;mt++)
#pragma unroll
        for (int nt=0;nt<2;nt++)
#pragma unroll
            for (int q=0;q<4;q++) acc[mt][nt][q]=0.f;

    for (int ch=0; ch<8; ch++) {
        int kc = ch*32;
#pragma unroll
        for (int l=0;l<2;l++) {
            int idx = tid + l*256;
            int row = idx>>3, q = (idx&7)*4;
            float4 v = *(const float4*)(x + (size_t)(tok0+row)*CC + kc + q);
            Xs[row][q]=v.x; Xs[row][q+1]=v.y; Xs[row][q+2]=v.z; Xs[row][q+3]=v.w;
            float4 w = *(const float4*)(src + (size_t)row*CC + kc + q);
            Bs[row][q]=w.x; Bs[row][q+1]=w.y; Bs[row][q+2]=w.z; Bs[row][q+3]=w.w;
        }
        __syncthreads();
#pragma unroll
        for (int k8=0;k8<4;k8++) {
            int kb = k8*8;
            uint32_t ah[2][4], al[2][4], bh[2][2], bl[2][2];
#pragma unroll
            for (int mt=0;mt<2;mt++) {
                int m0 = wm*32 + mt*16 + gid;
                hilo(Xs[m0][kb+tig],     ah[mt][0], al[mt][0]);
                hilo(Xs[m0+8][kb+tig],   ah[mt][1], al[mt][1]);
                hilo(Xs[m0][kb+tig+4],   ah[mt][2], al[mt][2]);
                hilo(Xs[m0+8][kb+tig+4], ah[mt][3], al[mt][3]);
            }
#pragma unroll
            for (int nt=0;nt<2;nt++) {
                int nl = wn*16 + nt*8 + gid;
                hilo(Bs[nl][kb+tig],   bh[nt][0], bl[nt][0]);
                hilo(Bs[nl][kb+tig+4], bh[nt][1], bl[nt][1]);
            }
#pragma unroll
            for (int mt=0;mt<2;mt++)
#pragma unroll
                for (int nt=0;nt<2;nt++) {
                    mma8(acc[mt][nt], ah[mt], bh[nt]);
                    mma8(acc[mt][nt], ah[mt], bl[nt]);
                    mma8(acc[mt][nt], al[mt], bh[nt]);
                }
        }
        __syncthreads();
    }
#pragma unroll
    for (int mt=0;mt<2;mt++)
#pragma unroll
        for (int nt=0;nt<2;nt++) {
            int col = wn*16 + nt*8 + 2*tig;
#pragma unroll
            for (int rr=0;rr<2;rr++) {
                int tok = tok0 + wm*32 + mt*16 + gid + rr*8;
                float v0 = acc[mt][nt][rr*2], v1 = acc[mt][nt][rr*2+1];
                if (mode == 0) {
                    g_XM[(size_t)tok*CC + colgrp*64 + col]   = v0;
                    g_XM[(size_t)tok*CC + colgrp*64 + col+1] = v1;
                } else {
                    g_xG[(size_t)tok*NE + col]   = v0;
                    g_xG[(size_t)tok*NE + col+1] = v1;
                }
            }
        }
}

// ================= xWtb + S0 =================
__global__ void k_xw(const float* __restrict__ x) {
    int warp = threadIdx.x>>5, lane = threadIdx.x&31;
    int n = blockIdx.x*8 + warp;
    float qd=0.f, xw=0.f;
#pragma unroll
    for (int m=0;m<8;m++) {
        int idx = lane + m*32;
        float xv = x[(size_t)n*CC+idx];
        qd += xv * g_XM[(size_t)n*CC+idx];
        xw += xv * g_Wtb[idx];
    }
#pragma unroll
    for (int o=16;o>=1;o>>=1) {
        qd += __shfl_xor_sync(0xffffffffu, qd, o);
        xw += __shfl_xor_sync(0xffffffffu, xw, o);
    }
    if (lane == 0) {
        g_xWtb[n] = xw;
        atomicAdd(&g_accd[0], (double)(qd + 2.f*xw + (float)g_bbd));
    }
}

// ================= resp (warp per token) + S1a + binning =================
__global__ void k_resp2(const float* __restrict__ u) {
    int warp = threadIdx.x>>5, lane = threadIdx.x&31;
    int n = blockIdx.x*8 + warp;
    int e0 = lane, e1 = lane + 32;
    float xg0 = g_xG[(size_t)n*NE+e0] + (float)g_bcd[e0];
    float xg1 = g_xG[(size_t)n*NE+e1] + (float)g_bcd[e1];
    float l0 = 2.f*xg0 - (float)g_cnormd[e0] - logf(-logf(u[(size_t)n*NE+e0]));
    float l1 = 2.f*xg1 - (float)g_cnormd[e1] - logf(-logf(u[(size_t)n*NE+e1]));
    float m = fmaxf(l0, l1);
#pragma unroll
    for (int o=16;o>=1;o>>=1) m = fmaxf(m, __shfl_xor_sync(0xffffffffu, m, o));
    float ex0 = expf(l0 - m), ex1 = expf(l1 - m);
    float S = ex0 + ex1;
#pragma unroll
    for (int o=16;o>=1;o>>=1) S += __shfl_xor_sync(0xffffffffu, S, o);
    float r0 = ex0 / S, r1 = ex1 / S;
    g_resp[(size_t)n*NE+e0] = r0;
    g_resp[(size_t)n*NE+e1] = r1;
    float s1 = r0*xg0 + r1*xg1;
#pragma unroll
    for (int o=16;o>=1;o>>=1) s1 += __shfl_xor_sync(0xffffffffu, s1, o);
    if (lane == 0) atomicAdd(&g_accd[1], (double)s1);
    if (r0 > 1e-9f) {
        int p = atomicAdd(&g_cnt[e0], 1);
        g_tokn[e0*NN+p] = n; g_tokr[e0*NN+p] = r0;
    }
    if (r1 > 1e-9f) {
        int p = atomicAdd(&g_cnt[e1], 1);
        g_tokn[e1*NN+p] = n; g_tokr[e1*NN+p] = r1;
    }
}

// ================= A=R^T X, B2=R^T XM, Q=R^T R (hi/lo), s, t =================
__global__ void __launch_bounds__(256) k_RX(const float* __restrict__ x) {
    __shared__ float Rs[32][68];
    __shared__ float Xs[32][260];
    __shared__ float Ms[32][260];
    __shared__ float tw[32];
    int tid=threadIdx.x, warp=tid>>5, lane=tid&31, gid=lane>>2, tig=lane&3;
    int n0 = blockIdx.x * 128;
    float accA[4][4][4], accB[4][4][4], accQ[4][4];
#pragma unroll
    for (int mt=0;mt<4;mt++) {
#pragma unroll
        for (int nt=0;nt<4;nt++)
#pragma unroll
            for (int q=0;q<4;q++) { accA[mt][nt][q]=0.f; accB[mt][nt][q]=0.f; }
#pragma unroll
        for (int q=0;q<4;q++) accQ[mt][q]=0.f;
    }
    float sp=0.f, tp=0.f;

    for (int cchunk=0; cchunk<4; cchunk++) {
        int nb = n0 + cchunk*32;
#pragma unroll
        for (int l=0;l<8;l++) {
            int idx = tid + l*256;
            int row = idx>>6, e2 = idx&63;
            Rs[row][e2] = g_resp[(size_t)(nb+row)*NE + e2];
        }
#pragma unroll
        for (int l=0;l<8;l++) {
            int idx = tid + l*256;
            int row = idx>>6, q = (idx&63)*4;
            float4 v = *(const float4*)(x + (size_t)(nb+row)*CC + q);
            Xs[row][q]=v.x; Xs[row][q+1]=v.y; Xs[row][q+2]=v.z; Xs[row][q+3]=v.w;
            float4 w = *(const float4*)(g_XM + (size_t)(nb+row)*CC + q);
            Ms[row][q]=w.x; Ms[row][q+1]=w.y; Ms[row][q+2]=w.z; Ms[row][q+3]=w.w;
        }
        if (tid < 32) tw[tid] = g_xWtb[nb+tid];
        __syncthreads();
        if (tid < 64) {
            for (int k=0;k<32;k++) { float rv = Rs[k][tid]; sp += rv; tp += rv*tw[k]; }
        }
#pragma unroll
        for (int k8=0;k8<4;k8++) {
            int kb = k8*8;
            uint32_t am[4][4], amh[4][4], aml[4][4];
#pragma unroll
            for (int mt=0;mt<4;mt++) {
                int m0 = mt*16;
                float v0 = Rs[kb+tig][m0+gid],   v1 = Rs[kb+tig][m0+gid+8];
                float v2 = Rs[kb+tig+4][m0+gid], v3 = Rs[kb+tig+4][m0+gid+8];
                am[mt][0]=fb(v0); am[mt][1]=fb(v1); am[mt][2]=fb(v2); am[mt][3]=fb(v3);
                hilo(v0, amh[mt][0], aml[mt][0]); hilo(v1, amh[mt][1], aml[mt][1]);
                hilo(v2, amh[mt][2], aml[mt][2]); hilo(v3, amh[mt][3], aml[mt][3]);
            }
#pragma unroll
            for (int nt=0;nt<4;nt++) {
                int c = warp*32 + nt*8 + gid;
                uint32_t bx[2] = { fb(Xs[kb+tig][c]), fb(Xs[kb+tig+4][c]) };
                uint32_t bm[2] = { fb(Ms[kb+tig][c]), fb(Ms[kb+tig+4][c]) };
#pragma unroll
                for (int mt=0;mt<4;mt++) { mma8(accA[mt][nt], am[mt], bx); mma8(accB[mt][nt], am[mt], bm); }
            }
            {
                int eq = warp*8 + gid;
                uint32_t bqh[2], bql[2];
                hilo(Rs[kb+tig][eq],   bqh[0], bql[0]);
                hilo(Rs[kb+tig+4][eq], bqh[1], bql[1]);
#pragma unroll
                for (int mt=0;mt<4;mt++) {
                    mma8(accQ[mt], amh[mt], bqh);
                    mma8(accQ[mt], amh[mt], bql);
                    mma8(accQ[mt], aml[mt], bqh);
                }
            }
        }
        __syncthreads();
    }
#pragma unroll
    for (int mt=0;mt<4;mt++) {
#pragma unroll
        for (int nt=0;nt<4;nt++) {
            int e = mt*16 + gid;
            int c = warp*32 + nt*8 + 2*tig;
            atomicAdd(&g_A[e*CC+c],        accA[mt][nt][0]);
            atomicAdd(&g_A[e*CC+c+1],      accA[mt][nt][1]);
            atomicAdd(&g_A[(e+8)*CC+c],    accA[mt][nt][2]);
            atomicAdd(&g_A[(e+8)*CC+c+1],  accA[mt][nt][3]);
            atomicAdd(&g_B2[e*CC+c],       accB[mt][nt][0]);
            atomicAdd(&g_B2[e*CC+c+1],     accB[mt][nt][1]);
            atomicAdd(&g_B2[(e+8)*CC+c],   accB[mt][nt][2]);
            atomicAdd(&g_B2[(e+8)*CC+c+1], accB[mt][nt][3]);
        }
        int e = mt*16 + gid;
        int eq = warp*8 + 2*tig;
        atomicAdd(&g_Q[e*NE+eq],       accQ[mt][0]);
        atomicAdd(&g_Q[e*NE+eq+1],     accQ[mt][1]);
        atomicAdd(&g_Q[(e+8)*NE+eq],   accQ[mt][2]);
        atomicAdd(&g_Q[(e+8)*NE+eq+1], accQ[mt][3]);
    }
    if (tid < 64) { atomicAdd(&g_s[tid], sp); atomicAdd(&g_t[tid], tp); }
}

// ================= Cnew = decay*Cents + gam*(A@W^T + s b^T) =================
__global__ void __launch_bounds__(256) k_cnew(const float* __restrict__ W,
                                              const float* __restrict__ cents,
                                              const float* __restrict__ bvec) {
    __shared__ float As[64][36];
    __shared__ float Ws[128][36];
    __shared__ float ss[64];
    int tid=threadIdx.x, warp=tid>>5, lane=tid&31, gid=lane>>2, tig=lane&3;
    int d0 = blockIdx.x * 128;
    if (tid < 64) ss[tid] = g_s[tid];
    float acc[4][2][4];
#pragma unroll
    for (int mt=0;mt<4;mt++)
#pragma unroll
        for (int nt=0;nt<2;nt++)
#pragma unroll
            for (int q=0;q<4;q++) acc[mt][nt][q]=0.f;

    for (int ch=0; ch<8; ch++) {
        int kc = ch*32;
#pragma unroll
        for (int l=0;l<2;l++) {
            int idx = tid + l*256;
            int row = idx>>3, q = (idx&7)*4;
            float4 v = *(const float4*)(g_A + (size_t)row*CC + kc + q);
            As[row][q]=v.x; As[row][q+1]=v.y; As[row][q+2]=v.z; As[row][q+3]=v.w;
        }
#pragma unroll
        for (int l=0;l<4;l++) {
            int idx = tid + l*256;
            int row = idx>>3, q = (idx&7)*4;
            float4 v = *(const float4*)(W + (size_t)(d0+row)*CC + kc + q);
            Ws[row][q]=v.x; Ws[row][q+1]=v.y; Ws[row][q+2]=v.z; Ws[row][q+3]=v.w;
        }
        __syncthreads();
#pragma unroll
        for (int k8=0;k8<4;k8++) {
            int kb = k8*8;
            uint32_t a[4][4], b[2][2];
#pragma unroll
            for (int mt=0;mt<4;mt++) {
                int e = mt*16 + gid;
                a[mt][0]=fb(As[e][kb+tig]);   a[mt][1]=fb(As[e+8][kb+tig]);
                a[mt][2]=fb(As[e][kb+tig+4]); a[mt][3]=fb(As[e+8][kb+tig+4]);
            }
#pragma unroll
            for (int nt=0;nt<2;nt++) {
                int dl = warp*16 + nt*8 + gid;
                b[nt][0]=fb(Ws[dl][kb+tig]); b[nt][1]=fb(Ws[dl][kb+tig+4]);
            }
#pragma unroll
            for (int mt=0;mt<4;mt++)
#pragma unroll
                for (int nt=0;nt<2;nt++) mma8(acc[mt][nt], a[mt], b[nt]);
        }
        __syncthreads();
    }
#pragma unroll
    for (int mt=0;mt<4;mt++)
#pragma unroll
        for (int nt=0;nt<2;nt++) {
            int e = mt*16 + gid;
            int d = d0 + warp*16 + nt*8 + 2*tig;
            float b0 = bvec[d], b1 = bvec[d+1];
            g_Cnew[(size_t)e*DD+d]       = DECAYv*cents[(size_t)e*DD+d]       + GAMv*(acc[mt][nt][0] + ss[e]*b0);
            g_Cnew[(size_t)e*DD+d+1]     = DECAYv*cents[(size_t)e*DD+d+1]     + GAMv*(acc[mt][nt][1] + ss[e]*b1);
            g_Cnew[(size_t)(e+8)*DD+d]   = DECAYv*cents[(size_t)(e+8)*DD+d]   + GAMv*(acc[mt][nt][2] + ss[e+8]*b0);
            g_Cnew[(size_t)(e+8)*DD+d+1] = DECAYv*cents[(size_t)(e+8)*DD+d+1] + GAMv*(acc[mt][nt][3] + ss[e+8]*b1);
        }
}

// ================= tail: H (hi/lo) | binned output GEMM =================
__global__ void __launch_bounds__(256) k_tail(float* __restrict__ out) {
    __shared__ __align__(16) char smp[70400];
    int b = blockIdx.x;
    int tid=threadIdx.x, warp=tid>>5, lane=tid&31, gid=lane>>2, tig=lane&3;
    if (b < 128) {
        // ---- H = Cnew Cnew^T (hi/lo) ----
        float (*Cs)[36] = (float (*)[36])smp;
        int d0 = b * 512;
        float acc[4][4];
#pragma unroll
        for (int mt=0;mt<4;mt++)
#pragma unroll
            for (int q=0;q<4;q++) acc[mt][q]=0.f;

        for (int ch=0; ch<16; ch++) {
            int dbase = d0 + ch*32;
#pragma unroll
            for (int l=0;l<2;l++) {
                int idx = tid + l*256;
                int e = idx>>3, q = (idx&7)*4;
                float4 v = *(const float4*)(g_Cnew + (size_t)e*DD + dbase + q);
                Cs[e][q]=v.x; Cs[e][q+1]=v.y; Cs[e][q+2]=v.z; Cs[e][q+3]=v.w;
            }
            __syncthreads();
#pragma unroll
            for (int k8=0;k8<4;k8++) {
                int kb = k8*8;
                uint32_t ah[4][4], al[4][4], bh[2], bl[2];
#pragma unroll
                for (int mt=0;mt<4;mt++) {
                    int e = mt*16 + gid;
                    hilo(Cs[e][kb+tig],     ah[mt][0], al[mt][0]);
                    hilo(Cs[e+8][kb+tig],   ah[mt][1], al[mt][1]);
                    hilo(Cs[e][kb+tig+4],   ah[mt][2], al[mt][2]);
                    hilo(Cs[e+8][kb+tig+4], ah[mt][3], al[mt][3]);
                }
                int n0 = warp*8 + gid;
                hilo(Cs[n0][kb+tig],   bh[0], bl[0]);
                hilo(Cs[n0][kb+tig+4], bh[1], bl[1]);
#pragma unroll
                for (int mt=0;mt<4;mt++) {
                    mma8(acc[mt], ah[mt], bh);
                    mma8(acc[mt], ah[mt], bl);
                    mma8(acc[mt], al[mt], bh);
                }
            }
            __syncthreads();
        }
#pragma unroll
        for (int mt=0;mt<4;mt++) {
            int e = mt*16 + gid;
            int n = warp*8 + 2*tig;
            atomicAdd(&g_H[e*NE+n],       acc[mt][0]);
            atomicAdd(&g_H[e*NE+n+1],     acc[mt][1]);
            atomicAdd(&g_H[(e+8)*NE+n],   acc[mt][2]);
            atomicAdd(&g_H[(e+8)*NE+n+1], acc[mt][3]);
        }
    } else {
        // ---- binned output ----
        int idx0 = b - 128;
        int e = idx0 & 63;
        int cnt = g_cnt[e];
        int a0 = (idx0 >> 6) * 32;
        if (a0 >= cnt) return;
        float (*ys)[260] = (float (*)[260])smp;
        float (*Cw)[36]  = (float (*)[36])(smp + 33280);
        int* stok        = (int*)(smp + 33280 + 36864);
        int wm = warp>>2, wn = warp&3;
#pragma unroll
        for (int l=0;l<8;l++) {
            int idx = tid + l*256;
            int row = idx >> 6, q = idx & 63;
            int aa = a0 + row;
            float r = 0.f; int n = 0;
            float4 v = make_float4(0.f,0.f,0.f,0.f);
            if (aa < cnt) {
                n = g_tokn[e*NN+aa]; r = g_tokr[e*NN+aa];
                v = *(const float4*)(g_Y + (size_t)n*CC + q*4);
            }
            ys[row][q*4]=r*v.x; ys[row][q*4+1]=r*v.y; ys[row][q*4+2]=r*v.z; ys[row][q*4+3]=r*v.w;
            if (q == 0) stok[row] = n;
        }
        __syncthreads();
        float acc[8][4];
#pragma unroll
        for (int nt=0;nt<8;nt++)
#pragma unroll
            for (int q=0;q<4;q++) acc[nt][q]=0.f;

        for (int ch=0; ch<8; ch++) {
            int kc = ch*32;
#pragma unroll
            for (int l=0;l<8;l++) {
                int idx = tid + l*256;
                int row = idx >> 3, q = (idx & 7)*4;
                float4 v = *(const float4*)(g_Cnew + (size_t)e*DD + (size_t)row*CC + kc + q);
                Cw[row][q]=v.x; Cw[row][q+1]=v.y; Cw[row][q+2]=v.z; Cw[row][q+3]=v.w;
            }
            __syncthreads();
#pragma unroll
            for (int k8=0;k8<4;k8++) {
                int kb = k8*8;
                uint32_t ah[4], al[4];
                int m0 = wm*16 + gid;
                hilo(ys[m0][kc+kb+tig],     ah[0], al[0]);
                hilo(ys[m0+8][kc+kb+tig],   ah[1], al[1]);
                hilo(ys[m0][kc+kb+tig+4],   ah[2], al[2]);
                hilo(ys[m0+8][kc+kb+tig+4], ah[3], al[3]);
#pragma unroll
                for (int nt=0;nt<8;nt++) {
                    int nc = wn*64 + nt*8 + gid;
                    uint32_t bh[2], bl[2];
                    hilo(Cw[nc][kb+tig],   bh[0], bl[0]);
                    hilo(Cw[nc][kb+tig+4], bh[1], bl[1]);
                    mma8(acc[nt], ah, bh);
                    mma8(acc[nt], ah, bl);
                    mma8(acc[nt], al, bh);
                }
            }
            __syncthreads();
        }
        int t0 = wm*16 + gid;
        int r0 = stok[t0], r1 = stok[t0+8];
#pragma unroll
        for (int nt=0;nt<8;nt++) {
            int i = wn*64 + nt*8 + 2*tig;
            atomicAdd(out + (size_t)r0*ROUT + i,   acc[nt][0]);
            atomicAdd(out + (size_t)r0*ROUT + i+1, acc[nt][1]);
            atomicAdd(out + (size_t)r1*ROUT + i,   acc[nt][2]);
            atomicAdd(out + (size_t)r1*ROUT + i+1, acc[nt][3]);
        }
    }
}

// ================= final: bias | loss =================
__global__ void k_fin(float* __restrict__ out, const float* __restrict__ pwB, int out_size) {
    int b = blockIdx.x, tid = threadIdx.x;
    if (b < NN) {
        out[(size_t)b*ROUT + tid] += pwB[tid];
        return;
    }
    __shared__ float red[256];
    __shared__ float lsh;
    float p = 0.f;
    for (int idx = tid; idx < NE*CC; idx += 256) {
        int e = idx >> 8, c = idx & 255;
        p += g_A[idx] * (g_B2[idx] + g_s[e]*g_Wtb[c]);
    }
    if (tid < NE) p += g_s[tid]*(g_t[tid] + (float)g_bbd*g_s[tid]);
    float q = 0.f;
    for (int idx = tid; idx < NE*NE; idx += 256) q += g_H[idx]*g_Q[idx];
    red[tid] = p; __syncthreads();
    for (int s=128;s>=1;s>>=1) { if (tid<s) red[tid]+=red[tid+s]; __syncthreads(); }
    float psum = red[0]; __syncthreads();
    red[tid] = q; __syncthreads();
    for (int s=128;s>=1;s>>=1) { if (tid<s) red[tid]+=red[tid+s]; __syncthreads(); }
    if (tid == 0) {
        float S1 = DECAYv*(float)g_accd[1] + GAMv*psum;
        lsh = COMMITv * ((float)g_accd[0] - 2.f*S1 + red[0]) / ((float)NN * (float)DD);
    }
    __syncthreads();
    for (int i = NN*ROUT + tid; i < out_size; i += 256) out[i] = lsh;
}

extern "C" void kernel_launch(void* const* d_in, const int* in_sizes, int n_in,
                              void* d_out, int out_size) {
    const float* x     = (const float*)d_in[0];
    const float* u     = (const float*)d_in[1];
    const float* W     = (const float*)d_in[2];
    const float* bvec  = (const float*)d_in[3];
    const float* pw1   = (const float*)d_in[4];
    const float* pwB   = (const float*)d_in[5];
    const float* cents = (const float*)d_in[6];
    float* out = (float*)d_out;

    k_zero<<<2048, 256>>>(out);
    k_p1<<<320, 256>>>(W, cents, bvec, x, pw1);
    k_big2<<<160, 256>>>(x);
    k_xw<<<256, 256>>>(x);
    k_resp2<<<256, 256>>>(u);
    k_RX<<<16, 256>>>(x);
    k_cnew<<<512, 256>>>(W, cents, bvec);
    k_tail<<<128 + 64*64, 256>>>(out);
    k_fin<<<NN + 1, 256>>>(out, pwB, out_size);
}